// round 2
// baseline (speedup 1.0000x reference)
#include <cuda_runtime.h>
#include <cuda_bf16.h>

#define NN 4096
#define DIN 512
#define DH1 256
#define DH2 64
#define ALPHA 0.2f

// ---------------- device scratch (no allocations allowed) ----------------
__device__ float    g_h0[NN * DH1];
__device__ float    g_hidden[NN * DH1];
__device__ float    g_h1[NN * DH2];
__device__ float    g_h2[NN * DH2];
__device__ float    g_mean[NN * DH2];
__device__ float    g_logstd[NN * DH2];
__device__ float    g_Z[NN * DH2];
__device__ float4   g_rowvals[NN];
__device__ float4   g_colvals[NN];
__device__ unsigned g_adjbits[NN * (NN / 32)];
__device__ float    g_pacc[2 * NN * DH1];   // 8 MB: max of 2*N*256 and 4*N*64
__device__ float    g_pden[4 * NN];

// ---------------- pack adjacency into bitmask (2 MB, L2-resident) --------
__global__ void pack_adj_kernel(const int* __restrict__ adj, unsigned* __restrict__ bits) {
    int idx = blockIdx.x * 256 + threadIdx.x;          // one thread per adj element
    unsigned b = __ballot_sync(0xffffffffu, adj[idx] > 0);
    if ((threadIdx.x & 31) == 0) bits[idx >> 5] = b;
}

// ---------------- generic tiled fp32 GEMM: C[M,Nc] = A[M,K] @ B[K,Nc] ----
__global__ __launch_bounds__(256) void gemm64_kernel(
    const float* __restrict__ A, const float* __restrict__ B, float* __restrict__ C,
    int M, int K, int Nc)
{
    __shared__ float As[16][68];
    __shared__ float Bs[16][68];
    const int tid = threadIdx.x;
    const int tx = tid & 15, ty = tid >> 4;
    const int m0 = blockIdx.y * 64, n0 = blockIdx.x * 64;
    const int am = tid >> 2;
    const int ak = (tid & 3) * 4;
    const int bk = tid >> 4;
    const int bn = (tid & 15) * 4;

    float acc[4][4] = {};
    for (int k0 = 0; k0 < K; k0 += 16) {
        float4 av = *(const float4*)&A[(size_t)(m0 + am) * K + k0 + ak];
        float4 bv = *(const float4*)&B[(size_t)(k0 + bk) * Nc + n0 + bn];
        __syncthreads();
        As[ak + 0][am] = av.x; As[ak + 1][am] = av.y;
        As[ak + 2][am] = av.z; As[ak + 3][am] = av.w;
        *(float4*)&Bs[bk][bn] = bv;
        __syncthreads();
#pragma unroll
        for (int k = 0; k < 16; ++k) {
            float4 a4 = *(float4*)&As[k][ty * 4];
            float4 b4 = *(float4*)&Bs[k][tx * 4];
            acc[0][0] += a4.x * b4.x; acc[0][1] += a4.x * b4.y; acc[0][2] += a4.x * b4.z; acc[0][3] += a4.x * b4.w;
            acc[1][0] += a4.y * b4.x; acc[1][1] += a4.y * b4.y; acc[1][2] += a4.y * b4.z; acc[1][3] += a4.y * b4.w;
            acc[2][0] += a4.z * b4.x; acc[2][1] += a4.z * b4.y; acc[2][2] += a4.z * b4.z; acc[2][3] += a4.z * b4.w;
            acc[3][0] += a4.w * b4.x; acc[3][1] += a4.w * b4.y; acc[3][2] += a4.w * b4.z; acc[3][3] += a4.w * b4.w;
        }
    }
#pragma unroll
    for (int i = 0; i < 4; ++i) {
        float4 v = make_float4(acc[i][0], acc[i][1], acc[i][2], acc[i][3]);
        *(float4*)&C[(size_t)(m0 + ty * 4 + i) * Nc + n0 + tx * 4] = v;
    }
}

// ---------------- per-row attention scalars: f1,f2 and their exps --------
// rowvals[i] = (-f1, exp(f1), exp(a*f1), 0); colvals[j] = (f2, exp(f2), exp(a*f2), 0)
__global__ void vals_kernel(const float* __restrict__ h, const float* __restrict__ a,
                            int D, float4* __restrict__ rowvals, float4* __restrict__ colvals)
{
    int warp = (blockIdx.x * blockDim.x + threadIdx.x) >> 5;
    int lane = threadIdx.x & 31;
    if (warp >= NN) return;
    float s1 = 0.f, s2 = 0.f;
    for (int d = lane; d < D; d += 32) {
        float hv = h[(size_t)warp * D + d];
        s1 += hv * a[d];
        s2 += hv * a[D + d];
    }
#pragma unroll
    for (int o = 16; o; o >>= 1) {
        s1 += __shfl_xor_sync(0xffffffffu, s1, o);
        s2 += __shfl_xor_sync(0xffffffffu, s2, o);
    }
    if (lane == 0) {
        rowvals[warp] = make_float4(-s1, expf(s1), expf(ALPHA * s1), 0.f);
        colvals[warp] = make_float4(s2, expf(s2), expf(ALPHA * s2), 0.f);
    }
}

// ---------------- fused masked-softmax attention (no per-pair exp) -------
// Computes partial (unnormalized) out[i,:] = sum_j w_ij * h[j,:] and den[i] = sum_j w_ij
// with w_ij = adj_ij ? ( (f1_i+f2_j>0) ? P_i*E_j : Q_i*F_j ) : 0
template<int D, int TC, int CPT, int TI, int RPT, int BI, int BJ>
__global__ __launch_bounds__(128) void attn_kernel(
    const float* __restrict__ h,
    const float4* __restrict__ rowvals,
    const float4* __restrict__ colvals,
    const unsigned* __restrict__ adjbits,
    float* __restrict__ pacc,
    float* __restrict__ pden)
{
    __shared__ float4 hs4[BJ * D / 4];
    __shared__ float4 cvs[BJ];
    float* hs = (float*)hs4;

    const int tid = threadIdx.x;
    const int tc = tid / TI;
    const int ti = tid % TI;
    const int rowbase = blockIdx.x * BI;
    const int split = blockIdx.y;
    const int nsplit = gridDim.y;
    const int jcnt = NN / nsplit;
    const int jbeg = split * jcnt;

    float acc[RPT][CPT];
    float den[RPT];
    float negf1[RPT], Pv[RPT], Qv[RPT];
    int rows[RPT];
#pragma unroll
    for (int r = 0; r < RPT; ++r) {
        rows[r] = rowbase + ti + r * TI;
        float4 rv = rowvals[rows[r]];
        negf1[r] = rv.x; Pv[r] = rv.y; Qv[r] = rv.z;
        den[r] = 0.f;
#pragma unroll
        for (int c = 0; c < CPT; ++c) acc[r][c] = 0.f;
    }

    for (int jt = 0; jt < jcnt; jt += BJ) {
        const int j0 = jbeg + jt;
        __syncthreads();
        const float4* src = (const float4*)(h + (size_t)j0 * D);
#pragma unroll
        for (int it = 0; it < BJ * D / (4 * 128); ++it)
            hs4[tid + it * 128] = src[tid + it * 128];
        if (tid < BJ) cvs[tid] = colvals[j0 + tid];
        __syncthreads();

        unsigned mw[RPT][BJ / 32];
#pragma unroll
        for (int r = 0; r < RPT; ++r)
#pragma unroll
            for (int w = 0; w < BJ / 32; ++w)
                mw[r][w] = adjbits[(size_t)rows[r] * (NN / 32) + (j0 >> 5) + w];

#pragma unroll 1
        for (int w = 0; w < BJ / 32; ++w) {
#pragma unroll 4
            for (int b = 0; b < 32; ++b) {
                const int jj = w * 32 + b;
                float4 c = cvs[jj];                    // (f2_j, E_j, F_j, _)
                float wv[RPT];
#pragma unroll
                for (int r = 0; r < RPT; ++r) {
                    bool p = c.x > negf1[r];           // f1_i + f2_j > 0
                    float e = p ? c.y : c.z;
                    float sc = p ? Pv[r] : Qv[r];
                    float wgt = e * sc;
                    wgt = ((mw[r][w] >> b) & 1u) ? wgt : 0.f;
                    den[r] += wgt;
                    wv[r] = wgt;
                }
                const float4* hp = (const float4*)(hs + jj * D + tc * CPT);
#pragma unroll
                for (int cb = 0; cb < CPT / 4; ++cb) {
                    float4 hv = hp[cb];
#pragma unroll
                    for (int r = 0; r < RPT; ++r) {
                        acc[r][cb * 4 + 0] += wv[r] * hv.x;
                        acc[r][cb * 4 + 1] += wv[r] * hv.y;
                        acc[r][cb * 4 + 2] += wv[r] * hv.z;
                        acc[r][cb * 4 + 3] += wv[r] * hv.w;
                    }
                }
            }
        }
    }

#pragma unroll
    for (int r = 0; r < RPT; ++r) {
        float* pa = pacc + ((size_t)split * NN + rows[r]) * D + tc * CPT;
#pragma unroll
        for (int cb = 0; cb < CPT / 4; ++cb)
            ((float4*)pa)[cb] = make_float4(acc[r][cb * 4 + 0], acc[r][cb * 4 + 1],
                                            acc[r][cb * 4 + 2], acc[r][cb * 4 + 3]);
        if (tc == 0) pden[split * NN + rows[r]] = den[r];
    }
}

// ---------------- combine split partials + normalize ---------------------
__global__ void combine_kernel(const float* __restrict__ pacc, const float* __restrict__ pden,
                               float* __restrict__ out, int D, int nsplit)
{
    int idx = blockIdx.x * blockDim.x + threadIdx.x;    // float4 index
    int total = NN * D / 4;
    if (idx >= total) return;
    int row = idx / (D / 4);
    float4 s = make_float4(0.f, 0.f, 0.f, 0.f);
    float dd = 0.f;
    for (int sp = 0; sp < nsplit; ++sp) {
        float4 v = ((const float4*)pacc)[(size_t)sp * total + idx];
        s.x += v.x; s.y += v.y; s.z += v.z; s.w += v.w;
        dd += pden[sp * NN + row];
    }
    float inv = 1.f / dd;
    s.x *= inv; s.y *= inv; s.z *= inv; s.w *= inv;
    ((float4*)out)[idx] = s;
}

// ---------------- Z = noise * exp(logstd) + mean -------------------------
__global__ void z_kernel(const float* __restrict__ noise, const float* __restrict__ logstd,
                         const float* __restrict__ mean, float* __restrict__ Z)
{
    int idx = blockIdx.x * blockDim.x + threadIdx.x;
    if (idx >= NN * DH2) return;
    Z[idx] = noise[idx] * expf(logstd[idx]) + mean[idx];
}

// ---------------- A = sigmoid(Z @ Z^T), symmetric ------------------------
__global__ __launch_bounds__(256) void zzt_kernel(const float* __restrict__ Z, float* __restrict__ out)
{
    const int bi = blockIdx.y, bj = blockIdx.x;
    if (bj < bi) return;
    __shared__ float ZiT[64][68];
    __shared__ float ZjT[64][68];
    const int tid = threadIdx.x;
    const int r = tid >> 2;
    const int kq = (tid & 3) * 16;
    const int i0 = bi * 64, j0 = bj * 64;
#pragma unroll
    for (int q = 0; q < 4; ++q) {
        int k = kq + q * 4;
        float4 v = *(const float4*)&Z[(size_t)(i0 + r) * DH2 + k];
        ZiT[k + 0][r] = v.x; ZiT[k + 1][r] = v.y; ZiT[k + 2][r] = v.z; ZiT[k + 3][r] = v.w;
        float4 u = *(const float4*)&Z[(size_t)(j0 + r) * DH2 + k];
        ZjT[k + 0][r] = u.x; ZjT[k + 1][r] = u.y; ZjT[k + 2][r] = u.z; ZjT[k + 3][r] = u.w;
    }
    __syncthreads();
    const int tx = tid & 15, ty = tid >> 4;
    float acc[4][4] = {};
#pragma unroll 16
    for (int k = 0; k < 64; ++k) {
        float4 a4 = *(float4*)&ZiT[k][ty * 4];
        float4 b4 = *(float4*)&ZjT[k][tx * 4];
        acc[0][0] += a4.x * b4.x; acc[0][1] += a4.x * b4.y; acc[0][2] += a4.x * b4.z; acc[0][3] += a4.x * b4.w;
        acc[1][0] += a4.y * b4.x; acc[1][1] += a4.y * b4.y; acc[1][2] += a4.y * b4.z; acc[1][3] += a4.y * b4.w;
        acc[2][0] += a4.z * b4.x; acc[2][1] += a4.z * b4.y; acc[2][2] += a4.z * b4.z; acc[2][3] += a4.z * b4.w;
        acc[3][0] += a4.w * b4.x; acc[3][1] += a4.w * b4.y; acc[3][2] += a4.w * b4.z; acc[3][3] += a4.w * b4.w;
    }
    float s[4][4];
#pragma unroll
    for (int i = 0; i < 4; ++i)
#pragma unroll
        for (int j = 0; j < 4; ++j) {
            float ex = __expf(-acc[i][j]);
            s[i][j] = __fdividef(1.f, 1.f + ex);
        }
#pragma unroll
    for (int i = 0; i < 4; ++i) {
        float4 v = make_float4(s[i][0], s[i][1], s[i][2], s[i][3]);
        *(float4*)&out[(size_t)(i0 + ty * 4 + i) * NN + j0 + tx * 4] = v;
    }
    if (bj > bi) {
#pragma unroll
        for (int j = 0; j < 4; ++j) {
            float4 v = make_float4(s[0][j], s[1][j], s[2][j], s[3][j]);
            *(float4*)&out[(size_t)(j0 + tx * 4 + j) * NN + i0 + ty * 4] = v;
        }
    }
}

// ---------------- host orchestration -------------------------------------
extern "C" void kernel_launch(void* const* d_in, const int* in_sizes, int n_in,
                              void* d_out, int out_size)
{
    const float* X     = (const float*)d_in[0];
    const int*   adj   = (const int*)  d_in[1];
    const float* noise = (const float*)d_in[2];
    const float* W0    = (const float*)d_in[3];
    const float* a0    = (const float*)d_in[4];
    const float* W1    = (const float*)d_in[5];
    const float* a1    = (const float*)d_in[6];
    const float* W2    = (const float*)d_in[7];
    const float* a2    = (const float*)d_in[8];
    float* out = (float*)d_out;

    float *p_h0, *p_hidden, *p_h1, *p_h2, *p_mean, *p_logstd, *p_Z, *p_pacc, *p_pden;
    float4 *p_rv, *p_cv;
    unsigned* p_bits;
    cudaGetSymbolAddress((void**)&p_h0, g_h0);
    cudaGetSymbolAddress((void**)&p_hidden, g_hidden);
    cudaGetSymbolAddress((void**)&p_h1, g_h1);
    cudaGetSymbolAddress((void**)&p_h2, g_h2);
    cudaGetSymbolAddress((void**)&p_mean, g_mean);
    cudaGetSymbolAddress((void**)&p_logstd, g_logstd);
    cudaGetSymbolAddress((void**)&p_Z, g_Z);
    cudaGetSymbolAddress((void**)&p_pacc, g_pacc);
    cudaGetSymbolAddress((void**)&p_pden, g_pden);
    cudaGetSymbolAddress((void**)&p_rv, g_rowvals);
    cudaGetSymbolAddress((void**)&p_cv, g_colvals);
    cudaGetSymbolAddress((void**)&p_bits, g_adjbits);

    // adjacency bitmask
    pack_adj_kernel<<<NN * NN / 256, 256>>>(adj, p_bits);

    // ---- layer 0: h0 = X@W0 ; hidden = attn(h0) ----
    gemm64_kernel<<<dim3(DH1 / 64, NN / 64), 256>>>(X, W0, p_h0, NN, DIN, DH1);
    vals_kernel<<<NN / 8, 256>>>(p_h0, a0, DH1, p_rv, p_cv);
    attn_kernel<DH1, 8, 32, 16, 2, 32, 32><<<dim3(NN / 32, 2), 128>>>(p_h0, p_rv, p_cv, p_bits, p_pacc, p_pden);
    combine_kernel<<<NN * DH1 / 4 / 256, 256>>>(p_pacc, p_pden, p_hidden, DH1, 2);

    // ---- layer 1 (mean) ----
    gemm64_kernel<<<dim3(DH2 / 64, NN / 64), 256>>>(p_hidden, W1, p_h1, NN, DH1, DH2);
    vals_kernel<<<NN / 8, 256>>>(p_h1, a1, DH2, p_rv, p_cv);
    attn_kernel<DH2, 4, 16, 32, 2, 64, 64><<<dim3(NN / 64, 4), 128>>>(p_h1, p_rv, p_cv, p_bits, p_pacc, p_pden);
    combine_kernel<<<NN * DH2 / 4 / 256, 256>>>(p_pacc, p_pden, p_mean, DH2, 4);

    // ---- layer 2 (logstd) ----
    gemm64_kernel<<<dim3(DH2 / 64, NN / 64), 256>>>(p_hidden, W2, p_h2, NN, DH1, DH2);
    vals_kernel<<<NN / 8, 256>>>(p_h2, a2, DH2, p_rv, p_cv);
    attn_kernel<DH2, 4, 16, 32, 2, 64, 64><<<dim3(NN / 64, 4), 128>>>(p_h2, p_rv, p_cv, p_bits, p_pacc, p_pden);
    combine_kernel<<<NN * DH2 / 4 / 256, 256>>>(p_pacc, p_pden, p_logstd, DH2, 4);

    // ---- Z and decoder ----
    z_kernel<<<NN * DH2 / 256, 256>>>(noise, p_logstd, p_mean, p_Z);
    zzt_kernel<<<dim3(NN / 64, NN / 64), 256>>>(p_Z, out);
}

// round 3
// speedup vs baseline: 1.1772x; 1.1772x over previous
#include <cuda_runtime.h>
#include <cuda_bf16.h>

#define NN 4096
#define DIN 512
#define DH1 256
#define DH2 64
#define ALPHA 0.2f

// ---------------- device scratch (no allocations allowed) ----------------
__device__ float    g_h0[NN * DH1];
__device__ float    g_hidden[NN * DH1];
__device__ float    g_h1[NN * DH2];
__device__ float    g_h2[NN * DH2];
__device__ float    g_mean[NN * DH2];
__device__ float    g_logstd[NN * DH2];
__device__ float    g_Z[NN * DH2];
__device__ float4   g_rowvals[NN];
__device__ float4   g_colvals[NN];
__device__ unsigned g_adjbits[NN * (NN / 32)];
__device__ float    g_pacc[8 * NN * DH1];   // 32 MB: max of 8*N*256 and 16*N*64
__device__ float    g_pden[16 * NN];

// ---------------- pack adjacency into bitmask (2 MB, L2-resident) --------
__global__ void pack_adj_kernel(const int* __restrict__ adj, unsigned* __restrict__ bits) {
    int idx = blockIdx.x * 256 + threadIdx.x;          // one thread per adj element
    unsigned b = __ballot_sync(0xffffffffu, adj[idx] > 0);
    if ((threadIdx.x & 31) == 0) bits[idx >> 5] = b;
}

// ---------------- generic tiled fp32 GEMM: C[M,Nc] = A[M,K] @ B[K,Nc] ----
__global__ __launch_bounds__(256) void gemm64_kernel(
    const float* __restrict__ A, const float* __restrict__ B, float* __restrict__ C,
    int M, int K, int Nc)
{
    __shared__ float As[16][68];
    __shared__ float Bs[16][68];
    const int tid = threadIdx.x;
    const int tx = tid & 15, ty = tid >> 4;
    const int m0 = blockIdx.y * 64, n0 = blockIdx.x * 64;
    const int am = tid >> 2;
    const int ak = (tid & 3) * 4;
    const int bk = tid >> 4;
    const int bn = (tid & 15) * 4;

    float acc[4][4] = {};
    for (int k0 = 0; k0 < K; k0 += 16) {
        float4 av = *(const float4*)&A[(size_t)(m0 + am) * K + k0 + ak];
        float4 bv = *(const float4*)&B[(size_t)(k0 + bk) * Nc + n0 + bn];
        __syncthreads();
        As[ak + 0][am] = av.x; As[ak + 1][am] = av.y;
        As[ak + 2][am] = av.z; As[ak + 3][am] = av.w;
        *(float4*)&Bs[bk][bn] = bv;
        __syncthreads();
#pragma unroll
        for (int k = 0; k < 16; ++k) {
            float4 a4 = *(float4*)&As[k][ty * 4];
            float4 b4 = *(float4*)&Bs[k][tx * 4];
            acc[0][0] += a4.x * b4.x; acc[0][1] += a4.x * b4.y; acc[0][2] += a4.x * b4.z; acc[0][3] += a4.x * b4.w;
            acc[1][0] += a4.y * b4.x; acc[1][1] += a4.y * b4.y; acc[1][2] += a4.y * b4.z; acc[1][3] += a4.y * b4.w;
            acc[2][0] += a4.z * b4.x; acc[2][1] += a4.z * b4.y; acc[2][2] += a4.z * b4.z; acc[2][3] += a4.z * b4.w;
            acc[3][0] += a4.w * b4.x; acc[3][1] += a4.w * b4.y; acc[3][2] += a4.w * b4.z; acc[3][3] += a4.w * b4.w;
        }
    }
#pragma unroll
    for (int i = 0; i < 4; ++i) {
        float4 v = make_float4(acc[i][0], acc[i][1], acc[i][2], acc[i][3]);
        *(float4*)&C[(size_t)(m0 + ty * 4 + i) * Nc + n0 + tx * 4] = v;
    }
}

// ---------------- per-row attention scalars: f1,f2 and their exps --------
// rowvals[i] = (-f1, exp(f1), exp(a*f1), 0); colvals[j] = (f2, exp(f2), exp(a*f2), 0)
__global__ void vals_kernel(const float* __restrict__ h, const float* __restrict__ a,
                            int D, float4* __restrict__ rowvals, float4* __restrict__ colvals)
{
    int warp = (blockIdx.x * blockDim.x + threadIdx.x) >> 5;
    int lane = threadIdx.x & 31;
    if (warp >= NN) return;
    float s1 = 0.f, s2 = 0.f;
    for (int d = lane; d < D; d += 32) {
        float hv = h[(size_t)warp * D + d];
        s1 += hv * a[d];
        s2 += hv * a[D + d];
    }
#pragma unroll
    for (int o = 16; o; o >>= 1) {
        s1 += __shfl_xor_sync(0xffffffffu, s1, o);
        s2 += __shfl_xor_sync(0xffffffffu, s2, o);
    }
    if (lane == 0) {
        rowvals[warp] = make_float4(-s1, expf(s1), expf(ALPHA * s1), 0.f);
        colvals[warp] = make_float4(s2, expf(s2), expf(ALPHA * s2), 0.f);
    }
}

// ---------------- fused masked-softmax attention (no per-pair exp) -------
// Computes partial (unnormalized) out[i,:] = sum_j w_ij * h[j,:] and den[i] = sum_j w_ij
// with w_ij = adj_ij ? ( (f1_i+f2_j>0) ? P_i*E_j : Q_i*F_j ) : 0
template<int D, int TC, int CPT, int TI, int RPT, int BI, int BJ>
__global__ __launch_bounds__(128) void attn_kernel(
    const float* __restrict__ h,
    const float4* __restrict__ rowvals,
    const float4* __restrict__ colvals,
    const unsigned* __restrict__ adjbits,
    float* __restrict__ pacc,
    float* __restrict__ pden)
{
    __shared__ float4 hs4[BJ * D / 4];
    __shared__ float4 cvs[BJ];
    float* hs = (float*)hs4;

    const int tid = threadIdx.x;
    const int tc = tid / TI;
    const int ti = tid % TI;
    const int rowbase = blockIdx.x * BI;
    const int split = blockIdx.y;
    const int nsplit = gridDim.y;
    const int jcnt = NN / nsplit;
    const int jbeg = split * jcnt;

    float acc[RPT][CPT];
    float den[RPT];
    float negf1[RPT], Pv[RPT], Qv[RPT];
    int rows[RPT];
#pragma unroll
    for (int r = 0; r < RPT; ++r) {
        rows[r] = rowbase + ti + r * TI;
        float4 rv = rowvals[rows[r]];
        negf1[r] = rv.x; Pv[r] = rv.y; Qv[r] = rv.z;
        den[r] = 0.f;
#pragma unroll
        for (int c = 0; c < CPT; ++c) acc[r][c] = 0.f;
    }

    for (int jt = 0; jt < jcnt; jt += BJ) {
        const int j0 = jbeg + jt;
        __syncthreads();
        const float4* src = (const float4*)(h + (size_t)j0 * D);
#pragma unroll
        for (int it = 0; it < BJ * D / (4 * 128); ++it)
            hs4[tid + it * 128] = src[tid + it * 128];
        if (tid < BJ) cvs[tid] = colvals[j0 + tid];
        __syncthreads();

        unsigned mw[RPT][BJ / 32];
#pragma unroll
        for (int r = 0; r < RPT; ++r)
#pragma unroll
            for (int w = 0; w < BJ / 32; ++w)
                mw[r][w] = adjbits[(size_t)rows[r] * (NN / 32) + (j0 >> 5) + w];

#pragma unroll 1
        for (int w = 0; w < BJ / 32; ++w) {
#pragma unroll 4
            for (int b = 0; b < 32; ++b) {
                const int jj = w * 32 + b;
                float4 c = cvs[jj];                    // (f2_j, E_j, F_j, _)
                float wv[RPT];
#pragma unroll
                for (int r = 0; r < RPT; ++r) {
                    bool p = c.x > negf1[r];           // f1_i + f2_j > 0
                    float e = p ? c.y : c.z;
                    float sc = p ? Pv[r] : Qv[r];
                    float wgt = e * sc;
                    wgt = ((mw[r][w] >> b) & 1u) ? wgt : 0.f;
                    den[r] += wgt;
                    wv[r] = wgt;
                }
                const float4* hp = (const float4*)(hs + jj * D + tc * CPT);
#pragma unroll
                for (int cb = 0; cb < CPT / 4; ++cb) {
                    float4 hv = hp[cb];
#pragma unroll
                    for (int r = 0; r < RPT; ++r) {
                        acc[r][cb * 4 + 0] += wv[r] * hv.x;
                        acc[r][cb * 4 + 1] += wv[r] * hv.y;
                        acc[r][cb * 4 + 2] += wv[r] * hv.z;
                        acc[r][cb * 4 + 3] += wv[r] * hv.w;
                    }
                }
            }
        }
    }

#pragma unroll
    for (int r = 0; r < RPT; ++r) {
        float* pa = pacc + ((size_t)split * NN + rows[r]) * D + tc * CPT;
#pragma unroll
        for (int cb = 0; cb < CPT / 4; ++cb)
            ((float4*)pa)[cb] = make_float4(acc[r][cb * 4 + 0], acc[r][cb * 4 + 1],
                                            acc[r][cb * 4 + 2], acc[r][cb * 4 + 3]);
        if (tc == 0) pden[split * NN + rows[r]] = den[r];
    }
}

// ---------------- combine split partials + normalize ---------------------
__global__ void combine_kernel(const float* __restrict__ pacc, const float* __restrict__ pden,
                               float* __restrict__ out, int D, int nsplit)
{
    int idx = blockIdx.x * blockDim.x + threadIdx.x;    // float4 index
    int total = NN * D / 4;
    if (idx >= total) return;
    int row = idx / (D / 4);
    float4 s = make_float4(0.f, 0.f, 0.f, 0.f);
    float dd = 0.f;
    for (int sp = 0; sp < nsplit; ++sp) {
        float4 v = ((const float4*)pacc)[(size_t)sp * total + idx];
        s.x += v.x; s.y += v.y; s.z += v.z; s.w += v.w;
        dd += pden[sp * NN + row];
    }
    float inv = 1.f / dd;
    s.x *= inv; s.y *= inv; s.z *= inv; s.w *= inv;
    ((float4*)out)[idx] = s;
}

// ---------------- Z = noise * exp(logstd) + mean -------------------------
__global__ void z_kernel(const float* __restrict__ noise, const float* __restrict__ logstd,
                         const float* __restrict__ mean, float* __restrict__ Z)
{
    int idx = blockIdx.x * blockDim.x + threadIdx.x;
    if (idx >= NN * DH2) return;
    Z[idx] = noise[idx] * expf(logstd[idx]) + mean[idx];
}

// ---------------- A = sigmoid(Z @ Z^T), symmetric ------------------------
__global__ __launch_bounds__(256) void zzt_kernel(const float* __restrict__ Z, float* __restrict__ out)
{
    const int bi = blockIdx.y, bj = blockIdx.x;
    if (bj < bi) return;
    __shared__ float ZiT[64][68];
    __shared__ float ZjT[64][68];
    const int tid = threadIdx.x;
    const int r = tid >> 2;
    const int kq = (tid & 3) * 16;
    const int i0 = bi * 64, j0 = bj * 64;
#pragma unroll
    for (int q = 0; q < 4; ++q) {
        int k = kq + q * 4;
        float4 v = *(const float4*)&Z[(size_t)(i0 + r) * DH2 + k];
        ZiT[k + 0][r] = v.x; ZiT[k + 1][r] = v.y; ZiT[k + 2][r] = v.z; ZiT[k + 3][r] = v.w;
        float4 u = *(const float4*)&Z[(size_t)(j0 + r) * DH2 + k];
        ZjT[k + 0][r] = u.x; ZjT[k + 1][r] = u.y; ZjT[k + 2][r] = u.z; ZjT[k + 3][r] = u.w;
    }
    __syncthreads();
    const int tx = tid & 15, ty = tid >> 4;
    float acc[4][4] = {};
#pragma unroll 16
    for (int k = 0; k < 64; ++k) {
        float4 a4 = *(float4*)&ZiT[k][ty * 4];
        float4 b4 = *(float4*)&ZjT[k][tx * 4];
        acc[0][0] += a4.x * b4.x; acc[0][1] += a4.x * b4.y; acc[0][2] += a4.x * b4.z; acc[0][3] += a4.x * b4.w;
        acc[1][0] += a4.y * b4.x; acc[1][1] += a4.y * b4.y; acc[1][2] += a4.y * b4.z; acc[1][3] += a4.y * b4.w;
        acc[2][0] += a4.z * b4.x; acc[2][1] += a4.z * b4.y; acc[2][2] += a4.z * b4.z; acc[2][3] += a4.z * b4.w;
        acc[3][0] += a4.w * b4.x; acc[3][1] += a4.w * b4.y; acc[3][2] += a4.w * b4.z; acc[3][3] += a4.w * b4.w;
    }
    float s[4][4];
#pragma unroll
    for (int i = 0; i < 4; ++i)
#pragma unroll
        for (int j = 0; j < 4; ++j) {
            float ex = __expf(-acc[i][j]);
            s[i][j] = __fdividef(1.f, 1.f + ex);
        }
#pragma unroll
    for (int i = 0; i < 4; ++i) {
        float4 v = make_float4(s[i][0], s[i][1], s[i][2], s[i][3]);
        *(float4*)&out[(size_t)(i0 + ty * 4 + i) * NN + j0 + tx * 4] = v;
    }
    if (bj > bi) {
#pragma unroll
        for (int j = 0; j < 4; ++j) {
            float4 v = make_float4(s[0][j], s[1][j], s[2][j], s[3][j]);
            *(float4*)&out[(size_t)(j0 + tx * 4 + j) * NN + i0 + ty * 4] = v;
        }
    }
}

// ---------------- host orchestration -------------------------------------
extern "C" void kernel_launch(void* const* d_in, const int* in_sizes, int n_in,
                              void* d_out, int out_size)
{
    const float* X     = (const float*)d_in[0];
    const int*   adj   = (const int*)  d_in[1];
    const float* noise = (const float*)d_in[2];
    const float* W0    = (const float*)d_in[3];
    const float* a0    = (const float*)d_in[4];
    const float* W1    = (const float*)d_in[5];
    const float* a1    = (const float*)d_in[6];
    const float* W2    = (const float*)d_in[7];
    const float* a2    = (const float*)d_in[8];
    float* out = (float*)d_out;

    float *p_h0, *p_hidden, *p_h1, *p_h2, *p_mean, *p_logstd, *p_Z, *p_pacc, *p_pden;
    float4 *p_rv, *p_cv;
    unsigned* p_bits;
    cudaGetSymbolAddress((void**)&p_h0, g_h0);
    cudaGetSymbolAddress((void**)&p_hidden, g_hidden);
    cudaGetSymbolAddress((void**)&p_h1, g_h1);
    cudaGetSymbolAddress((void**)&p_h2, g_h2);
    cudaGetSymbolAddress((void**)&p_mean, g_mean);
    cudaGetSymbolAddress((void**)&p_logstd, g_logstd);
    cudaGetSymbolAddress((void**)&p_Z, g_Z);
    cudaGetSymbolAddress((void**)&p_pacc, g_pacc);
    cudaGetSymbolAddress((void**)&p_pden, g_pden);
    cudaGetSymbolAddress((void**)&p_rv, g_rowvals);
    cudaGetSymbolAddress((void**)&p_cv, g_colvals);
    cudaGetSymbolAddress((void**)&p_bits, g_adjbits);

    // adjacency bitmask
    pack_adj_kernel<<<NN * NN / 256, 256>>>(adj, p_bits);

    // ---- layer 0: h0 = X@W0 ; hidden = attn(h0) ----
    gemm64_kernel<<<dim3(DH1 / 64, NN / 64), 256>>>(X, W0, p_h0, NN, DIN, DH1);
    vals_kernel<<<NN / 8, 256>>>(p_h0, a0, DH1, p_rv, p_cv);
    attn_kernel<DH1, 8, 32, 16, 2, 32, 32><<<dim3(NN / 32, 8), 128>>>(p_h0, p_rv, p_cv, p_bits, p_pacc, p_pden);
    combine_kernel<<<NN * DH1 / 4 / 256, 256>>>(p_pacc, p_pden, p_hidden, DH1, 8);

    // ---- layer 1 (mean) ----
    gemm64_kernel<<<dim3(DH2 / 64, NN / 64), 256>>>(p_hidden, W1, p_h1, NN, DH1, DH2);
    vals_kernel<<<NN / 8, 256>>>(p_h1, a1, DH2, p_rv, p_cv);
    attn_kernel<DH2, 4, 16, 32, 2, 64, 64><<<dim3(NN / 64, 16), 128>>>(p_h1, p_rv, p_cv, p_bits, p_pacc, p_pden);
    combine_kernel<<<NN * DH2 / 4 / 256, 256>>>(p_pacc, p_pden, p_mean, DH2, 16);

    // ---- layer 2 (logstd) ----
    gemm64_kernel<<<dim3(DH2 / 64, NN / 64), 256>>>(p_hidden, W2, p_h2, NN, DH1, DH2);
    vals_kernel<<<NN / 8, 256>>>(p_h2, a2, DH2, p_rv, p_cv);
    attn_kernel<DH2, 4, 16, 32, 2, 64, 64><<<dim3(NN / 64, 16), 128>>>(p_h2, p_rv, p_cv, p_bits, p_pacc, p_pden);
    combine_kernel<<<NN * DH2 / 4 / 256, 256>>>(p_pacc, p_pden, p_logstd, DH2, 16);

    // ---- Z and decoder ----
    z_kernel<<<NN * DH2 / 256, 256>>>(noise, p_logstd, p_mean, p_Z);
    zzt_kernel<<<dim3(NN / 64, NN / 64), 256>>>(p_Z, out);
}